// round 14
// baseline (speedup 1.0000x reference)
#include <cuda_runtime.h>
#include <cuda_fp16.h>

#define IN_DIM   32768
#define OUT_DIM  32768
#define BATCH    2048
#define RPB      2            // batch rows per block (half2-interleaved in smem)
#define NTHREADS 512
#define COL_SEGS (OUT_DIM / 4 / NTHREADS)   // 16
#define SMEM_BYTES (IN_DIM * 4)             // one half2 plane: rows 0,1 interleaved

// Packed metadata, SoA (12 B / column total):
//   g_pidx[j] : ia | ib<<16
//   g_pcx[j]  : (c0, ca)  as half2 bits
//   g_pcy[j]  : (cb, cab) as half2 bits
__device__ unsigned g_pidx[OUT_DIM];
__device__ unsigned g_pcx[OUT_DIM];
__device__ unsigned g_pcy[OUT_DIM];

__constant__ float GC[16][4] = {
    {0.f,0.f,0.f,0.f}, {0.f,0.f,0.f,1.f}, {0.f,1.f,0.f,-1.f}, {0.f,1.f,0.f,0.f},
    {0.f,0.f,1.f,-1.f}, {0.f,0.f,1.f,0.f}, {0.f,1.f,1.f,-2.f}, {0.f,1.f,1.f,-1.f},
    {1.f,-1.f,-1.f,1.f}, {1.f,-1.f,-1.f,2.f}, {1.f,0.f,-1.f,0.f}, {1.f,0.f,-1.f,1.f},
    {1.f,-1.f,0.f,0.f}, {1.f,-1.f,0.f,1.f}, {1.f,0.f,0.f,-1.f}, {1.f,0.f,0.f,0.f}
};

// prep: softmax coeffs -> fp16 pack, idx pair -> 16+16 bit pack.
// idx dtype detected per-block from the first 512 32-bit words of idx_a:
// little-endian int64 < 32768 -> all odd words zero; int32 random -> not.
__global__ void prep_kernel(const float* __restrict__ w,
                            const void* __restrict__ pa,
                            const void* __restrict__ pb) {
    const unsigned* wa = (const unsigned*)pa;
    int is64 = !__syncthreads_or(wa[2 * threadIdx.x + 1] != 0u);

    int j = blockIdx.x * blockDim.x + threadIdx.x;
    if (j >= OUT_DIM) return;

    float wv[16];
    const float4* w4 = reinterpret_cast<const float4*>(w) + (size_t)j * 4;
#pragma unroll
    for (int q = 0; q < 4; q++) {
        float4 v = w4[q];
        wv[4*q+0] = v.x; wv[4*q+1] = v.y; wv[4*q+2] = v.z; wv[4*q+3] = v.w;
    }
    float m = wv[0];
#pragma unroll
    for (int i = 1; i < 16; i++) m = fmaxf(m, wv[i]);
    float s = 0.f;
#pragma unroll
    for (int i = 0; i < 16; i++) { wv[i] = __expf(wv[i] - m); s += wv[i]; }
    float inv = 1.f / s;

    float c0 = 0.f, ca = 0.f, cb = 0.f, cab = 0.f;
#pragma unroll
    for (int i = 0; i < 16; i++) {
        float p = wv[i];
        c0  = fmaf(p, GC[i][0], c0);
        ca  = fmaf(p, GC[i][1], ca);
        cb  = fmaf(p, GC[i][2], cb);
        cab = fmaf(p, GC[i][3], cab);
    }
    c0 *= inv; ca *= inv; cb *= inv; cab *= inv;

    __half2 h01 = __floats2half2_rn(c0, ca);
    __half2 h23 = __floats2half2_rn(cb, cab);
    g_pcx[j] = *reinterpret_cast<unsigned*>(&h01);
    g_pcy[j] = *reinterpret_cast<unsigned*>(&h23);

    unsigned ia, ib;
    if (is64) {
        ia = (unsigned)reinterpret_cast<const long long*>(pa)[j];
        ib = (unsigned)reinterpret_cast<const long long*>(pb)[j];
    } else {
        ia = (unsigned)reinterpret_cast<const int*>(pa)[j];
        ib = (unsigned)reinterpret_cast<const int*>(pb)[j];
    }
    g_pidx[j] = ia | (ib << 16);
}

extern __shared__ unsigned char smem_raw[];

// One column's contribution for one batch row (3 FMA)
__device__ __forceinline__ float gate3(float a, float b, float2 c01, float2 c23) {
    return fmaf(a, fmaf(c23.y, b, c01.y), fmaf(c23.x, b, c01.x));
}

__global__ void __launch_bounds__(NTHREADS, 1)
logic_main(const float* __restrict__ x, float* __restrict__ out) {
    half2* __restrict__ s01 = reinterpret_cast<half2*>(smem_raw);  // rows 0,1 interleaved

    const uint4* __restrict__ pidx4 = reinterpret_cast<const uint4*>(g_pidx);
    const uint4* __restrict__ pcx4  = reinterpret_cast<const uint4*>(g_pcx);
    const uint4* __restrict__ pcy4  = reinterpret_cast<const uint4*>(g_pcy);

    int r0 = blockIdx.x * RPB;   // BATCH % RPB == 0: no tail
    const int t0 = threadIdx.x;

    // ── Metadata pipeline prologue: seg 0's loads fly during the row-load
    //    phase and the barrier (independent of smem).
    uint4 ii = __ldg(&pidx4[t0]);
    uint4 cx = __ldg(&pcx4[t0]);
    uint4 cy = __ldg(&pcy4[t0]);

    // ── Row load: fp32 rows -> one fp16 half2 plane (streaming, read-once)
    const float4* x0 = reinterpret_cast<const float4*>(x + (size_t)r0 * IN_DIM);
    const float4* x1 = reinterpret_cast<const float4*>(x + (size_t)(r0 + 1) * IN_DIM);
#pragma unroll 4
    for (int i = threadIdx.x; i < IN_DIM / 4; i += NTHREADS) {
        float4 v0 = __ldcs(&x0[i]);
        float4 v1 = __ldcs(&x1[i]);
        union { half2 h[4]; float4 f; } u;
        u.h[0] = __floats2half2_rn(v0.x, v1.x);
        u.h[1] = __floats2half2_rn(v0.y, v1.y);
        u.h[2] = __floats2half2_rn(v0.z, v1.z);
        u.h[3] = __floats2half2_rn(v0.w, v1.w);
        *reinterpret_cast<float4*>(&s01[4*i]) = u.f;
    }
    __syncthreads();

    float4* o0 = reinterpret_cast<float4*>(out + (size_t)r0 * OUT_DIM);
    float4* o1 = o0 + OUT_DIM / 4;

    // ── Gather prologue for seg 0
    half2 ga[4], gb[4];
    {
        unsigned iw[4] = {ii.x, ii.y, ii.z, ii.w};
#pragma unroll
        for (int k = 0; k < 4; k++) {
            ga[k] = s01[iw[k] & 0xFFFFu];
            gb[k] = s01[iw[k] >> 16];
        }
    }

    // ── Main loop: depth-1 pipeline on BOTH metadata and gathers.
    //    While computing seg s (register-resident), seg s+1's meta LDGs and
    //    8 LDS gathers are in flight.  512 threads -> 128-reg budget.
    int t = t0;
#pragma unroll 4
    for (int seg = 0; seg < COL_SEGS; seg++) {
        const int last = (seg == COL_SEGS - 1);
        int tn = t + NTHREADS;

        // next seg's metadata
        uint4 n_ii, n_cx, n_cy;
        if (!last) {
            n_ii = __ldg(&pidx4[tn]);
            n_cx = __ldg(&pcx4[tn]);
            n_cy = __ldg(&pcy4[tn]);
        }

        // next seg's gathers — uses meta loaded one iteration ago... no:
        // n_ii just issued above has ~L2 latency; gathers for seg s+1 must use
        // the *already-arrived* idx from the previous rotation.  To keep a
        // depth-1 gather pipeline with depth-1 meta, gather from n_ii would
        // stall on it.  Instead: issue gathers for seg s+1 late (after compute
        // issues) so the LDS latency overlaps the stores + next compute head.
        unsigned cxw[4] = {cx.x, cx.y, cx.z, cx.w};
        unsigned cyw[4] = {cy.x, cy.y, cy.z, cy.w};

        float4 r_0, r_1;
        float* p0 = &r_0.x; float* p1 = &r_1.x;
#pragma unroll
        for (int k = 0; k < 4; k++) {
            float2 c01 = __half22float2(*reinterpret_cast<__half2*>(&cxw[k])); // c0, ca
            float2 c23 = __half22float2(*reinterpret_cast<__half2*>(&cyw[k])); // cb, cab
            float2 af = __half22float2(ga[k]), bf = __half22float2(gb[k]);
            p0[k] = gate3(af.x, bf.x, c01, c23);
            p1[k] = gate3(af.y, bf.y, c01, c23);
        }

        // issue next gathers between compute and stores (LDS latency overlaps
        // the STG issue + next iteration's meta handling)
        if (!last) {
            unsigned iw[4] = {n_ii.x, n_ii.y, n_ii.z, n_ii.w};
#pragma unroll
            for (int k = 0; k < 4; k++) {
                ga[k] = s01[iw[k] & 0xFFFFu];
                gb[k] = s01[iw[k] >> 16];
            }
        }

        __stcs(&o0[t], r_0);
        __stcs(&o1[t], r_1);

        ii = n_ii; cx = n_cx; cy = n_cy;
        t = tn;
    }
}

extern "C" void kernel_launch(void* const* d_in, const int* in_sizes, int n_in,
                              void* d_out, int out_size) {
    const float* x  = (const float*)d_in[0];
    const void*  ia = d_in[1];
    const void*  ib = d_in[2];
    const float* w  = (const float*)d_in[3];
    float* out = (float*)d_out;

    prep_kernel<<<OUT_DIM / 256, 256>>>(w, ia, ib);

    cudaFuncSetAttribute(logic_main, cudaFuncAttributeMaxDynamicSharedMemorySize, SMEM_BYTES);
    int grid = BATCH / RPB;   // 1024 blocks
    logic_main<<<grid, NTHREADS, SMEM_BYTES>>>(x, out);
}